// round 16
// baseline (speedup 1.0000x reference)
#include <cuda_runtime.h>
#include <cuda_bf16.h>

// ChamferLoss R15: R14 (37.6us, the first spill-free 4-warp/SMSP config) with
// prep/load slot reduction:
//  - p staged PRE-PACKED in SMEM as ull {-2p,-2p} (splat at staging, prep is
//    3 LDS.64 + 1 scalar + 1 pack per row instead of 4 LDS + 4 packs)
//  - qs array dropped: |q|^2 computed per j4 from the loaded packs (6 ops
//    amortized over 8 rows; one fewer LDS.128 per j4; frees 4KB SMEM so the
//    packed p fits the 48KB static limit)
//  - track d^2 directly (pn=-2p, psq=|p|^2)
// Layout unchanged: 512 thr, 16 warps = 4 row-blocks x 4 col-quarters,
// colmin[8] regs, 2 fully-unrolled LDS.128 col iterations, RG=8,
// REDUX.MIN row mins + SMEM atomicMin merges, fused deterministic tail.

#define NPTS    1024
#define THREADS 512
#define NWARPS  16
#define RG      8
#define CB_MAX  128

typedef unsigned long long ull;

#define PACK2(d, lo, hi) \
    asm("mov.b64 %0, {%1,%2};" : "=l"(d) : "f"(lo), "f"(hi))
#define UNPACK2(lo, hi, s) \
    asm("mov.b64 {%0,%1}, %2;" : "=f"(lo), "=f"(hi) : "l"(s))
#define FMA2(d, a, b, c) \
    asm("fma.rn.f32x2 %0, %1, %2, %3;" : "=l"(d) : "l"(a), "l"(b), "l"(c))
#define ADD2(d, a, b) \
    asm("add.rn.f32x2 %0, %1, %2;" : "=l"(d) : "l"(a), "l"(b))
#define MUL2(d, a, b) \
    asm("mul.rn.f32x2 %0, %1, %2;" : "=l"(d) : "l"(a), "l"(b))

__device__ float g_partials[CB_MAX];
__device__ int   g_done;   // zero-init; reset by last CTA each run

__global__ __launch_bounds__(THREADS, 1)
void chamfer_pair_kernel(const float* __restrict__ p, const float* __restrict__ q,
                         float* __restrict__ out, int cb_count) {
    __shared__ __align__(16) float qx_s[NPTS], qy_s[NPTS], qz_s[NPTS];
    __shared__ __align__(16) ull  pnx_s[NPTS], pny_s[NPTS], pnz_s[NPTS];
    __shared__ float ps_s[NPTS];
    __shared__ unsigned rowmin_sh[NPTS];
    __shared__ unsigned colmin_sh[NPTS];
    // Reduction scratch is overlaid on colmin_sh after it is consumed.

    const int cb   = blockIdx.x;
    const int tid  = threadIdx.x;
    const int warp = tid >> 5;
    const int lane = tid & 31;
    const int rb = warp >> 2;          // row block 0..3   (256 rows)
    const int cq = warp & 3;           // column quarter 0..3 (256 cols)
    const float INF = __int_as_float(0x7f800000);

    const float4* __restrict__ qp = reinterpret_cast<const float4*>(q) + (size_t)cb * NPTS;
    const float4* __restrict__ pp = reinterpret_cast<const float4*>(p) + (size_t)cb * NPTS;

    // Stage: q SoA (x,y,z); p packed {-2p,-2p} + |p|^2; init min buffers.
    for (int i = tid; i < NPTS; i += THREADS) {
        float4 v = qp[i];
        qx_s[i] = v.y; qy_s[i] = v.z; qz_s[i] = v.w;
        float4 u = pp[i];
        float a = -2.0f * u.y, b = -2.0f * u.z, c = -2.0f * u.w;
        ull t;
        PACK2(t, a, a); pnx_s[i] = t;
        PACK2(t, b, b); pny_s[i] = t;
        PACK2(t, c, c); pnz_s[i] = t;
        ps_s[i] = u.y * u.y + u.z * u.z + u.w * u.w;
        rowmin_sh[i] = 0x7f800000u;
        colmin_sh[i] = 0x7f800000u;
    }
    __syncthreads();

    // Lane owns cols cq*256 + j4*128 + lane*4 + {0..3}, j4 = 0..1 -> colmin[8].
    float colmin[8];
    #pragma unroll
    for (int j = 0; j < 8; ++j) colmin[j] = INF;

    const int colbase0 = (cq << 8) + (lane << 2);

    #pragma unroll 1
    for (int rg = 0; rg < 32; ++rg) {              // 32 groups of 8 rows
        const int row0 = rb * 256 + rg * RG;
        ull pnx2[RG], pny2[RG], pnz2[RG], psq2[RG];
        float rmin[RG];
        #pragma unroll
        for (int r = 0; r < RG; ++r) {
            int row = row0 + r;
            pnx2[r] = pnx_s[row];                  // LDS.64 broadcast
            pny2[r] = pny_s[row];
            pnz2[r] = pnz_s[row];
            float s = ps_s[row];
            PACK2(psq2[r], s, s);
            rmin[r] = INF;
        }
        #pragma unroll
        for (int j4 = 0; j4 < 2; ++j4) {           // 128 cols per j4; 256 total
            const int base = colbase0 + (j4 << 7); // 16B-aligned
            ulonglong2 xx = *reinterpret_cast<const ulonglong2*>(qx_s + base);
            ulonglong2 yy = *reinterpret_cast<const ulonglong2*>(qy_s + base);
            ulonglong2 zz = *reinterpret_cast<const ulonglong2*>(qz_s + base);
            // |q|^2 for 4 columns, computed once per j4 (amortized over 8 rows).
            ull s0, s1;
            MUL2(s0, xx.x, xx.x);
            FMA2(s0, yy.x, yy.x, s0);
            FMA2(s0, zz.x, zz.x, s0);
            MUL2(s1, xx.y, xx.y);
            FMA2(s1, yy.y, yy.y, s1);
            FMA2(s1, zz.y, zz.y, s1);
            #pragma unroll
            for (int r = 0; r < RG; ++r) {
                ull a01, a23;
                ADD2(a01, s0, psq2[r]);            // |q|^2 + |p|^2
                ADD2(a23, s1, psq2[r]);
                FMA2(a01, pnx2[r], xx.x, a01);     // - 2 p.q
                FMA2(a23, pnx2[r], xx.y, a23);
                FMA2(a01, pny2[r], yy.x, a01);
                FMA2(a23, pny2[r], yy.y, a23);
                FMA2(a01, pnz2[r], zz.x, a01);     // = d^2, 4 columns
                FMA2(a23, pnz2[r], zz.y, a23);
                float u0, u1, u2, u3;
                UNPACK2(u0, u1, a01);
                UNPACK2(u2, u3, a23);
                colmin[4 * j4 + 0] = fminf(colmin[4 * j4 + 0], u0);
                colmin[4 * j4 + 1] = fminf(colmin[4 * j4 + 1], u1);
                colmin[4 * j4 + 2] = fminf(colmin[4 * j4 + 2], u2);
                colmin[4 * j4 + 3] = fminf(colmin[4 * j4 + 3], u3);
                rmin[r] = fminf(rmin[r], fminf(fminf(u0, u1), fminf(u2, u3)));
            }
        }
        // Row mins over this warp's 256 cols: REDUX.MIN on clamped bits.
        #pragma unroll
        for (int r = 0; r < RG; ++r) {
            unsigned mb = __float_as_uint(fmaxf(rmin[r], 0.0f));
            mb = __reduce_min_sync(0xffffffffu, mb);
            if (lane == 0)
                atomicMin(&rowmin_sh[row0 + r], mb);  // merge 4 col-quarter warps
        }
    }

    // Column-min merge (4 row-block warps share each column quarter).
    #pragma unroll
    for (int j4 = 0; j4 < 2; ++j4) {
        #pragma unroll
        for (int k = 0; k < 4; ++k) {
            int c = colbase0 + (j4 << 7) + k;
            float v = fmaxf(colmin[4 * j4 + k], 0.0f);
            atomicMin(&colmin_sh[c], __float_as_uint(v));
        }
    }
    __syncthreads();

    // Per-thread partial: 2 rows + 2 cols each, fixed order. Values are
    // clamped min d^2; dist = sqrt(d2 + 1e-12).
    float acc = 0.0f;
    for (int i = tid; i < NPTS; i += THREADS) {
        acc += sqrtf(__uint_as_float(rowmin_sh[i]) + 1e-12f);
        acc += sqrtf(__uint_as_float(colmin_sh[i]) + 1e-12f);
    }
    #pragma unroll
    for (int off = 16; off > 0; off >>= 1)
        acc += __shfl_xor_sync(0xffffffffu, acc, off);
    __syncthreads();   // all reads of rowmin/colmin done; safe to overlay

    float* sredf = reinterpret_cast<float*>(colmin_sh);      // [0..15]
    int*   flagp = reinterpret_cast<int*>(colmin_sh) + 20;   // broadcast flag
    if (lane == 0) sredf[warp] = acc;
    __syncthreads();

    // Per-CTA total + done-ticket.
    if (tid == 0) {
        float total = 0.0f;
        #pragma unroll
        for (int w = 0; w < NWARPS; ++w) total += sredf[w];
        g_partials[cb] = total;
        __threadfence();                       // partial visible before ticket
        int prev = atomicAdd(&g_done, 1);
        *flagp = (prev == cb_count - 1) ? 1 : 0;
    }
    __syncthreads();

    // Last CTA: deterministic fixed-order final reduction over all pairs.
    if (*flagp) {
        __threadfence();                       // observe all partials (L2)
        float v = (tid < cb_count) ? __ldcg(&g_partials[tid]) : 0.0f;
        #pragma unroll
        for (int off = 16; off > 0; off >>= 1)
            v += __shfl_xor_sync(0xffffffffu, v, off);
        __syncthreads();                       // flag consumed by all
        if (lane == 0) sredf[warp] = v;
        __syncthreads();
        if (tid == 0) {
            float tot = 0.0f;
            #pragma unroll
            for (int w = 0; w < NWARPS; ++w) tot += sredf[w];
            out[0] = tot;
            g_done = 0;                        // reset for next graph replay
        }
    }
}

extern "C" void kernel_launch(void* const* d_in, const int* in_sizes, int n_in,
                              void* d_out, int out_size) {
    const float* p = (const float*)d_in[0];
    const float* q = (const float*)d_in[1];
    float* out = (float*)d_out;

    int cb = in_sizes[0] / (NPTS * 4);   // = 128 for (2,64,1024,4)
    if (cb > CB_MAX) cb = CB_MAX;

    chamfer_pair_kernel<<<cb, THREADS>>>(p, q, out, cb);
}